// round 3
// baseline (speedup 1.0000x reference)
#include <cuda_runtime.h>

// Shapes (fixed): x:[16,16,52,52] f32, W:[16,16,9,1], B:[16,16,1], out:[16,16,16]
#define NN 16
#define CC 16
#define HH 52
#define PLANE (HH*HH)      // 2704 floats = 676 float4 (13 float4 per row)
#define VPP (PLANE/4)      // 676
#define KK 9
#define M_TOT 22500.0f

__device__ float g_contrib[NN*CC*16];   // [n][c][o]

__global__ void __launch_bounds__(256, 4)
tvar_phase1(const float* __restrict__ x, const float* __restrict__ W)
{
    const int plane = blockIdx.x;          // n*16 + c
    const int c = plane & 15;
    const int t = threadIdx.x;
    const float4* xv = (const float4*)(x + plane * PLANE);

    // ---- front-batched, vectorized loads (max MLP) ----
    float4 d0 = __ldg(xv + t);
    float4 d1 = __ldg(xv + t + 256);
    float4 d2 = make_float4(0.f, 0.f, 0.f, 0.f);
    const bool has2 = (t < VPP - 512);     // t < 164
    if (has2) d2 = __ldg(xv + t + 512);

    __shared__ float sRow1[4], sRow2[4], sCol1[4], sCol2[4];  // rows/cols {0,1,50,51}
    __shared__ float sCor1[16], sCor2[16];                    // 4x4 corner elements
    __shared__ float sS1[KK], sS2[KK];
    __shared__ float sWarp[8][2];
    if (t < 4) { sRow1[t] = 0.f; sRow2[t] = 0.f; sCol1[t] = 0.f; sCol2[t] = 0.f; }
    __syncthreads();

    float t1 = 0.f, t2 = 0.f;

    // process one row-aligned float4 at vec index q
    auto process = [&](int q, float4 v) {
        const float s1 = v.x + v.y + v.z + v.w;
        const float s2 = v.x*v.x + v.y*v.y + v.z*v.z + v.w*v.w;
        t1 += s1; t2 += s2;
        const int h  = q / 13;
        const int wq = q - h * 13;
        int ri = -1;
        if (h == 0) ri = 0; else if (h == 1) ri = 1;
        else if (h == 50) ri = 2; else if (h == 51) ri = 3;
        if (ri >= 0) { atomicAdd(&sRow1[ri], s1); atomicAdd(&sRow2[ri], s2); }
        if (wq == 0) {            // cols 0,1 in lanes x,y
            atomicAdd(&sCol1[0], v.x); atomicAdd(&sCol1[1], v.y);
            atomicAdd(&sCol2[0], v.x*v.x); atomicAdd(&sCol2[1], v.y*v.y);
            if (ri >= 0) {
                sCor1[ri*4+0] = v.x;     sCor1[ri*4+1] = v.y;
                sCor2[ri*4+0] = v.x*v.x; sCor2[ri*4+1] = v.y*v.y;
            }
        } else if (wq == 12) {    // cols 50,51 in lanes z,w
            atomicAdd(&sCol1[2], v.z); atomicAdd(&sCol1[3], v.w);
            atomicAdd(&sCol2[2], v.z*v.z); atomicAdd(&sCol2[3], v.w*v.w);
            if (ri >= 0) {
                sCor1[ri*4+2] = v.z;     sCor1[ri*4+3] = v.w;
                sCor2[ri*4+2] = v.z*v.z; sCor2[ri*4+3] = v.w*v.w;
            }
        }
    };

    process(t, d0);
    process(t + 256, d1);
    if (has2) process(t + 512, d2);

    // ---- block-wide totals ----
#pragma unroll
    for (int off = 16; off > 0; off >>= 1) {
        t1 += __shfl_down_sync(0xffffffffu, t1, off);
        t2 += __shfl_down_sync(0xffffffffu, t2, off);
    }
    const int warp = t >> 5, lane = t & 31;
    if (lane == 0) { sWarp[warp][0] = t1; sWarp[warp][1] = t2; }
    __syncthreads();

    // ---- 9 window sums via inclusion-exclusion (threads 0..8) ----
    if (t < 9) {
        float tot1 = 0.f, tot2 = 0.f;
#pragma unroll
        for (int wI = 0; wI < 8; wI++) { tot1 += sWarp[wI][0]; tot2 += sWarp[wI][1]; }
        const int i = t / 3, j = t % 3;
        const float top1  = (i == 0) ? 0.f : (i == 1) ? sRow1[0] : sRow1[0] + sRow1[1];
        const float top2  = (i == 0) ? 0.f : (i == 1) ? sRow2[0] : sRow2[0] + sRow2[1];
        const float bot1  = (i == 0) ? sRow1[2] + sRow1[3] : (i == 1) ? sRow1[3] : 0.f;
        const float bot2  = (i == 0) ? sRow2[2] + sRow2[3] : (i == 1) ? sRow2[3] : 0.f;
        const float lef1  = (j == 0) ? 0.f : (j == 1) ? sCol1[0] : sCol1[0] + sCol1[1];
        const float lef2  = (j == 0) ? 0.f : (j == 1) ? sCol2[0] : sCol2[0] + sCol2[1];
        const float rig1  = (j == 0) ? sCol1[2] + sCol1[3] : (j == 1) ? sCol1[3] : 0.f;
        const float rig2  = (j == 0) ? sCol2[2] + sCol2[3] : (j == 1) ? sCol2[3] : 0.f;
        const int er0 = (i == 0) ? 2 : 0;
        const int er1 = (i == 2) ? 1 : 3;
        const int ec0 = (j == 0) ? 2 : 0;
        const int ec1 = (j == 2) ? 1 : 3;
        const float co1 = sCor1[er0*4+ec0] + sCor1[er0*4+ec1]
                        + sCor1[er1*4+ec0] + sCor1[er1*4+ec1];
        const float co2 = sCor2[er0*4+ec0] + sCor2[er0*4+ec1]
                        + sCor2[er1*4+ec0] + sCor2[er1*4+ec1];
        sS1[t] = tot1 - top1 - bot1 - lef1 - rig1 + co1;
        sS2[t] = tot2 - top2 - bot2 - lef2 - rig2 + co2;
    }
    __syncthreads();

    // ---- per-plane contribution for each output channel o ----
    if (t < 16) {
        const float* wp = W + (t * CC + c) * KK;   // W[o=t, c, :]
        float size = 0.f, A = 0.f, Bs = 0.f;
#pragma unroll
        for (int k = 0; k < KK; k++) {
            const float w = __ldg(wp + k);
            size += w;
            Bs = fmaf(w,     sS1[k], Bs);
            A  = fmaf(w * w, sS2[k], A);
        }
        g_contrib[plane * 16 + t] = (A - Bs * Bs * (1.0f / M_TOT)) / size;
    }
}

__global__ void __launch_bounds__(256, 1)
tvar_phase2(const float* __restrict__ B, float* __restrict__ out)
{
    const int t = threadIdx.x;
    __shared__ float sB[256];
    sB[t] = __ldg(B + t);

    const int n = t >> 4;                   // 0..15
    const int o = t & 15;                   // 0..15
    float acc = 0.f;
#pragma unroll
    for (int c = 0; c < 16; c++)
        acc += g_contrib[(n * 16 + c) * 16 + o];

    __syncthreads();
#pragma unroll
    for (int a = 0; a < 16; a++)
        out[a * 256 + t] = acc + sB[a * 16 + n];
}

extern "C" void kernel_launch(void* const* d_in, const int* in_sizes, int n_in,
                              void* d_out, int out_size)
{
    const float* x = (const float*)d_in[0];
    const float* W = (const float*)d_in[1];
    const float* B = (const float*)d_in[2];
    float* out = (float*)d_out;
    tvar_phase1<<<NN * CC, 256>>>(x, W);
    tvar_phase2<<<1, 256>>>(B, out);
}

// round 4
// speedup vs baseline: 1.1775x; 1.1775x over previous
#include <cuda_runtime.h>
#include <cstdint>

// Shapes (fixed): x:[16,16,52,52] f32, W:[16,16,9,1], B:[16,16,1], out:[16,16,16]
#define NN 16
#define CC 16
#define HH 52
#define PLANE (HH*HH)      // 2704 floats = 676 float4 (13 float4 per row)
#define VPP (PLANE/4)      // 676
#define KK 9
#define M_TOT 22500.0f
#define CLUSTER 8          // CTAs per cluster; cluster = one n; CTA handles 2 planes

__device__ __forceinline__ uint32_t smem_u32(const void* p) {
    uint32_t a;
    asm("{ .reg .u64 t; cvta.to.shared.u64 t, %1; cvt.u32.u64 %0, t; }" : "=r"(a) : "l"(p));
    return a;
}

__device__ __forceinline__ void dsmem_st_f32(uint32_t local_addr, uint32_t rank, float v) {
    uint32_t remote;
    asm volatile("mapa.shared::cluster.u32 %0, %1, %2;" : "=r"(remote) : "r"(local_addr), "r"(rank));
    asm volatile("st.shared::cluster.f32 [%0], %1;" :: "r"(remote), "f"(v) : "memory");
}

__global__ void __cluster_dims__(CLUSTER, 1, 1) __launch_bounds__(512, 1)
tvar_cluster(const float* __restrict__ x, const float* __restrict__ W,
             const float* __restrict__ B, float* __restrict__ out)
{
    __shared__ float sAll[CC*16];                 // rank-0 gathers contrib[c][o]
    __shared__ float sRow1[2][4], sRow2[2][4], sCol1[2][4], sCol2[2][4];
    __shared__ float sCor1[2][16], sCor2[2][16];
    __shared__ float sS1[2][KK], sS2[2][KK];
    __shared__ float sWarp[2][8][2];

    const int tid  = threadIdx.x;
    const int half = tid >> 8;                    // 0/1 : which plane of this CTA
    const int t    = tid & 255;
    uint32_t rank;
    asm("mov.u32 %0, %%cluster_ctarank;" : "=r"(rank));
    const int n = blockIdx.x / CLUSTER;
    const int c = (int)rank * 2 + half;
    const int plane = n * CC + c;

    const float4* xv = (const float4*)(x + plane * PLANE);

    // ---- front-batched loads: x data, W row, B value (max MLP, overlap all latency) ----
    float4 d0 = __ldg(xv + t);
    float4 d1 = __ldg(xv + t + 256);
    float4 d2 = make_float4(0.f, 0.f, 0.f, 0.f);
    const bool has2 = (t < VPP - 512);            // t < 164
    if (has2) d2 = __ldg(xv + t + 512);

    float wreg[KK];
    if (t < 16) {
        const float* wp = W + (t * CC + c) * KK;  // W[o=t, c, :]
#pragma unroll
        for (int k = 0; k < KK; k++) wreg[k] = __ldg(wp + k);
    }
    float bval = 0.f;
    if (rank == 0 && tid < 256) bval = __ldg(B + (tid >> 4) * CC + n);

    if (t < 4) {
        sRow1[half][t] = 0.f; sRow2[half][t] = 0.f;
        sCol1[half][t] = 0.f; sCol2[half][t] = 0.f;
    }
    __syncthreads();

    float t1 = 0.f, t2 = 0.f;

    auto process = [&](int q, float4 v) {
        const float s1 = v.x + v.y + v.z + v.w;
        const float s2 = v.x*v.x + v.y*v.y + v.z*v.z + v.w*v.w;
        t1 += s1; t2 += s2;
        const int h  = q / 13;
        const int wq = q - h * 13;
        int ri = -1;
        if (h == 0) ri = 0; else if (h == 1) ri = 1;
        else if (h == 50) ri = 2; else if (h == 51) ri = 3;
        if (ri >= 0) { atomicAdd(&sRow1[half][ri], s1); atomicAdd(&sRow2[half][ri], s2); }
        if (wq == 0) {
            atomicAdd(&sCol1[half][0], v.x);     atomicAdd(&sCol1[half][1], v.y);
            atomicAdd(&sCol2[half][0], v.x*v.x); atomicAdd(&sCol2[half][1], v.y*v.y);
            if (ri >= 0) {
                sCor1[half][ri*4+0] = v.x;     sCor1[half][ri*4+1] = v.y;
                sCor2[half][ri*4+0] = v.x*v.x; sCor2[half][ri*4+1] = v.y*v.y;
            }
        } else if (wq == 12) {
            atomicAdd(&sCol1[half][2], v.z);     atomicAdd(&sCol1[half][3], v.w);
            atomicAdd(&sCol2[half][2], v.z*v.z); atomicAdd(&sCol2[half][3], v.w*v.w);
            if (ri >= 0) {
                sCor1[half][ri*4+2] = v.z;     sCor1[half][ri*4+3] = v.w;
                sCor2[half][ri*4+2] = v.z*v.z; sCor2[half][ri*4+3] = v.w*v.w;
            }
        }
    };

    process(t, d0);
    process(t + 256, d1);
    if (has2) process(t + 512, d2);

    // ---- per-half block totals ----
#pragma unroll
    for (int off = 16; off > 0; off >>= 1) {
        t1 += __shfl_down_sync(0xffffffffu, t1, off);
        t2 += __shfl_down_sync(0xffffffffu, t2, off);
    }
    const int warp = t >> 5, lane = t & 31;
    if (lane == 0) { sWarp[half][warp][0] = t1; sWarp[half][warp][1] = t2; }
    __syncthreads();

    // ---- 9 window sums via inclusion-exclusion (threads 0..8 of each half) ----
    if (t < 9) {
        float tot1 = 0.f, tot2 = 0.f;
#pragma unroll
        for (int wI = 0; wI < 8; wI++) { tot1 += sWarp[half][wI][0]; tot2 += sWarp[half][wI][1]; }
        const int i = t / 3, j = t % 3;
        const float top1 = (i == 0) ? 0.f : (i == 1) ? sRow1[half][0] : sRow1[half][0] + sRow1[half][1];
        const float top2 = (i == 0) ? 0.f : (i == 1) ? sRow2[half][0] : sRow2[half][0] + sRow2[half][1];
        const float bot1 = (i == 0) ? sRow1[half][2] + sRow1[half][3] : (i == 1) ? sRow1[half][3] : 0.f;
        const float bot2 = (i == 0) ? sRow2[half][2] + sRow2[half][3] : (i == 1) ? sRow2[half][3] : 0.f;
        const float lef1 = (j == 0) ? 0.f : (j == 1) ? sCol1[half][0] : sCol1[half][0] + sCol1[half][1];
        const float lef2 = (j == 0) ? 0.f : (j == 1) ? sCol2[half][0] : sCol2[half][0] + sCol2[half][1];
        const float rig1 = (j == 0) ? sCol1[half][2] + sCol1[half][3] : (j == 1) ? sCol1[half][3] : 0.f;
        const float rig2 = (j == 0) ? sCol2[half][2] + sCol2[half][3] : (j == 1) ? sCol2[half][3] : 0.f;
        const int er0 = (i == 0) ? 2 : 0;
        const int er1 = (i == 2) ? 1 : 3;
        const int ec0 = (j == 0) ? 2 : 0;
        const int ec1 = (j == 2) ? 1 : 3;
        const float co1 = sCor1[half][er0*4+ec0] + sCor1[half][er0*4+ec1]
                        + sCor1[half][er1*4+ec0] + sCor1[half][er1*4+ec1];
        const float co2 = sCor2[half][er0*4+ec0] + sCor2[half][er0*4+ec1]
                        + sCor2[half][er1*4+ec0] + sCor2[half][er1*4+ec1];
        sS1[half][t] = tot1 - top1 - bot1 - lef1 - rig1 + co1;
        sS2[half][t] = tot2 - top2 - bot2 - lef2 - rig2 + co2;
    }
    __syncthreads();

    // ---- contrib[c][o] for o = t (threads 0..15 of each half) -> rank-0 DSMEM ----
    if (t < 16) {
        float size = 0.f, A = 0.f, Bs = 0.f;
#pragma unroll
        for (int k = 0; k < KK; k++) {
            const float w = wreg[k];
            size += w;
            Bs = fmaf(w,     sS1[half][k], Bs);
            A  = fmaf(w * w, sS2[half][k], A);
        }
        const float contrib = (A - Bs * Bs * (1.0f / M_TOT)) / size;
        const uint32_t dst = smem_u32(&sAll[c * 16 + t]);
        dsmem_st_f32(dst, 0u, contrib);
    }

    // ---- cluster barrier: release DSMEM writes, then rank-0 assembles output ----
    asm volatile("barrier.cluster.arrive.aligned;" ::: "memory");
    asm volatile("barrier.cluster.wait.aligned;"   ::: "memory");

    if (rank == 0 && tid < 256) {
        const int a = tid >> 4;
        const int o = tid & 15;
        float acc = 0.f;
#pragma unroll
        for (int cc = 0; cc < CC; cc++)
            acc += sAll[cc * 16 + o];
        out[a * 256 + n * 16 + o] = acc + bval;
    }
}

extern "C" void kernel_launch(void* const* d_in, const int* in_sizes, int n_in,
                              void* d_out, int out_size)
{
    const float* x = (const float*)d_in[0];
    const float* W = (const float*)d_in[1];
    const float* B = (const float*)d_in[2];
    float* out = (float*)d_out;
    tvar_cluster<<<NN * CLUSTER, 512>>>(x, W, B, out);
}

// round 5
// speedup vs baseline: 1.7909x; 1.5209x over previous
#include <cuda_runtime.h>
#include <cstdint>

// Shapes (fixed): x:[16,16,52,52] f32, W:[16,16,9,1], B:[16,16,1], out:[16,16,16]
#define NN 16
#define CC 16
#define HH 52
#define PLANE (HH*HH)      // 2704 floats = 676 float4
#define VPP (PLANE/4)      // 676
#define KK 9
#define M_TOT 22500.0f
#define CLUSTER 8          // cluster = one n; CTA = 2 planes (512 threads)

__device__ __forceinline__ uint32_t smem_u32(const void* p) {
    uint32_t a;
    asm("{ .reg .u64 t; cvta.to.shared.u64 t, %1; cvt.u32.u64 %0, t; }" : "=r"(a) : "l"(p));
    return a;
}

__device__ __forceinline__ float wred(float v) {
#pragma unroll
    for (int off = 16; off > 0; off >>= 1)
        v += __shfl_down_sync(0xffffffffu, v, off);
    return v;   // valid on lane 0
}

__global__ void __cluster_dims__(CLUSTER, 1, 1) __launch_bounds__(512, 1)
tvar_cluster(const float* __restrict__ x, const float* __restrict__ W,
             const float* __restrict__ B, float* __restrict__ out)
{
    __shared__ float sAll[CC*16];                 // rank0 gathers contrib[c][o]
    __shared__ unsigned long long sMbar;
    __shared__ float sWarp[2][8][2];
    __shared__ float sR1[2][4], sR2[2][4];        // row sums, rows {0,1,50,51}
    __shared__ float sC1[2][2][2][2], sC2[2][2][2][2]; // [half][pair][part][col]
    __shared__ float sCor1[2][16], sCor2[2][16];  // corner values / squares

    const int tid  = threadIdx.x;
    const int w    = tid >> 5;
    const int lane = tid & 31;
    const int half = tid >> 8;                    // which plane of this CTA
    const int t    = tid & 255;
    const int s    = w & 7;                       // warp role within half
    uint32_t rank;
    asm("mov.u32 %0, %%cluster_ctarank;" : "=r"(rank));
    const int n = blockIdx.x >> 3;
    const int c = (int)rank * 2 + half;
    const int plane = n * CC + c;
    const float*  xp = x + plane * PLANE;
    const float4* xv = (const float4*)xp;

    // ================= FRONT-BATCHED LOADS (everything in flight at once) ====
    float4 d0 = __ldg(xv + t);
    float4 d1 = __ldg(xv + t + 256);
    float4 d2 = make_float4(0.f, 0.f, 0.f, 0.f);
    const bool has2 = (t < VPP - 512);
    if (has2) d2 = __ldg(xv + t + 512);

    // strip re-loads (L1/L2 hits on same lines; no atomics anywhere)
    float4 rowv = make_float4(0.f, 0.f, 0.f, 0.f);
    float2 colv = make_float2(0.f, 0.f);
    if (s < 2) {                                  // row pairs {0,1} / {50,51}
        if (lane < 26) rowv = __ldg(xv + (s == 0 ? 0 : 650) + lane);
    } else if (s < 6) {                           // col pairs {0,1} / {50,51}
        const int pair = (s - 2) >> 1;
        const int r = lane + ((s - 2) & 1) * 32;
        if (r < HH) colv = __ldg((const float2*)(xp + r * HH + pair * 50));
    }

    float wreg[KK];
    float cor = 0.f;
    if (t < 16) {                                 // corners + W row
        const int ki = t >> 2, kj = t & 3;
        const int rr = (ki & 2 ? 50 : 0) + (ki & 1);
        const int cc2 = (kj & 2 ? 50 : 0) + (kj & 1);
        cor = __ldg(xp + rr * HH + cc2);
        const float* wp = W + (t * CC + c) * KK;  // W[o=t, c, :]
#pragma unroll
        for (int k = 0; k < KK; k++) wreg[k] = __ldg(wp + k);
    }
    float bval = 0.f;
    if (rank == 0 && tid < 256) bval = __ldg(B + (tid >> 4) * CC + n);

    // mbarrier init + early cluster publish (overlaps load latency)
    if (rank == 0 && tid == 0) {
        asm volatile("mbarrier.init.shared.b64 [%0], %1;"
                     :: "r"(smem_u32(&sMbar)), "r"(256u) : "memory");
    }
    asm volatile("barrier.cluster.arrive.aligned;" ::: "memory");

    // ================= TOTALS (per half-plane) ===============================
    float t1 = ((d0.x + d0.y) + (d0.z + d0.w))
             + ((d1.x + d1.y) + (d1.z + d1.w))
             + ((d2.x + d2.y) + (d2.z + d2.w));
    float t2 = d0.x*d0.x + d0.y*d0.y + d0.z*d0.z + d0.w*d0.w
             + d1.x*d1.x + d1.y*d1.y + d1.z*d1.z + d1.w*d1.w
             + d2.x*d2.x + d2.y*d2.y + d2.z*d2.z + d2.w*d2.w;
    t1 = wred(t1);
    t2 = wred(t2);
    if (lane == 0) { sWarp[half][s][0] = t1; sWarp[half][s][1] = t2; }

    // ================= STRIP SUMS (warp-local shuffle reductions) ============
    if (s < 2) {
        const float rs1 = (rowv.x + rowv.y) + (rowv.z + rowv.w);
        const float rs2 = rowv.x*rowv.x + rowv.y*rowv.y + rowv.z*rowv.z + rowv.w*rowv.w;
        const bool inA = (lane < 13);             // first row of pair
        const bool inB = (lane >= 13) && (lane < 26);
        float a1 = wred(inA ? rs1 : 0.f);
        float a2 = wred(inA ? rs2 : 0.f);
        float b1 = wred(inB ? rs1 : 0.f);
        float b2 = wred(inB ? rs2 : 0.f);
        if (lane == 0) {
            sR1[half][s*2+0] = a1; sR2[half][s*2+0] = a2;
            sR1[half][s*2+1] = b1; sR2[half][s*2+1] = b2;
        }
    } else if (s < 6) {
        const int pair = (s - 2) >> 1;
        const int part = (s - 2) & 1;
        float x1 = wred(colv.x);
        float x2 = wred(colv.x * colv.x);
        float y1 = wred(colv.y);
        float y2 = wred(colv.y * colv.y);
        if (lane == 0) {
            sC1[half][pair][part][0] = x1; sC2[half][pair][part][0] = x2;
            sC1[half][pair][part][1] = y1; sC2[half][pair][part][1] = y2;
        }
    }
    if (t < 16) { sCor1[half][t] = cor; sCor2[half][t] = cor * cor; }

    __syncthreads();
    asm volatile("barrier.cluster.wait.aligned;" ::: "memory");  // instant: all arrived long ago

    // ================= WINDOW SUMS + CONTRIB (warps 0 and 8 only) ============
    if (s == 0) {
        float s1v = 0.f, s2v = 0.f;
        if (lane < 9) {
            float tot1 = 0.f, tot2 = 0.f;
#pragma unroll
            for (int wi = 0; wi < 8; wi++) { tot1 += sWarp[half][wi][0]; tot2 += sWarp[half][wi][1]; }
            const int i = lane / 3, j = lane % 3;
            float R1[4], R2[4], C1[4], C2[4];
#pragma unroll
            for (int k = 0; k < 4; k++) {
                R1[k] = sR1[half][k]; R2[k] = sR2[half][k];
                C1[k] = sC1[half][k>>1][0][k&1] + sC1[half][k>>1][1][k&1];
                C2[k] = sC2[half][k>>1][0][k&1] + sC2[half][k>>1][1][k&1];
            }
            const float top1 = (i == 0) ? 0.f : (i == 1) ? R1[0] : R1[0] + R1[1];
            const float top2 = (i == 0) ? 0.f : (i == 1) ? R2[0] : R2[0] + R2[1];
            const float bot1 = (i == 0) ? R1[2] + R1[3] : (i == 1) ? R1[3] : 0.f;
            const float bot2 = (i == 0) ? R2[2] + R2[3] : (i == 1) ? R2[3] : 0.f;
            const float lef1 = (j == 0) ? 0.f : (j == 1) ? C1[0] : C1[0] + C1[1];
            const float lef2 = (j == 0) ? 0.f : (j == 1) ? C2[0] : C2[0] + C2[1];
            const float rig1 = (j == 0) ? C1[2] + C1[3] : (j == 1) ? C1[3] : 0.f;
            const float rig2 = (j == 0) ? C2[2] + C2[3] : (j == 1) ? C2[3] : 0.f;
            const int er0 = (i == 0) ? 2 : 0;
            const int er1 = (i == 2) ? 1 : 3;
            const int ec0 = (j == 0) ? 2 : 0;
            const int ec1 = (j == 2) ? 1 : 3;
            const float co1 = sCor1[half][er0*4+ec0] + sCor1[half][er0*4+ec1]
                            + sCor1[half][er1*4+ec0] + sCor1[half][er1*4+ec1];
            const float co2 = sCor2[half][er0*4+ec0] + sCor2[half][er0*4+ec1]
                            + sCor2[half][er1*4+ec0] + sCor2[half][er1*4+ec1];
            s1v = tot1 - top1 - bot1 - lef1 - rig1 + co1;
            s2v = tot2 - top2 - bot2 - lef2 - rig2 + co2;
        }
        // broadcast the 9 window sums to lanes 0..15 via shuffles (no block sync)
        float S1k[KK], S2k[KK];
#pragma unroll
        for (int k = 0; k < KK; k++) {
            S1k[k] = __shfl_sync(0xffffffffu, s1v, k);
            S2k[k] = __shfl_sync(0xffffffffu, s2v, k);
        }
        if (lane < 16) {
            float size = 0.f, A = 0.f, Bs = 0.f;
#pragma unroll
            for (int k = 0; k < KK; k++) {
                const float wv = wreg[k];
                size += wv;
                Bs = fmaf(wv,      S1k[k], Bs);
                A  = fmaf(wv * wv, S2k[k], A);
            }
            const float contrib = (A - Bs * Bs * (1.0f / M_TOT)) / size;
            // store into rank0's sAll[c][o] and release-arrive on rank0's mbarrier
            uint32_t dst = smem_u32(&sAll[c * 16 + lane]);
            uint32_t rem;
            asm("mapa.shared::cluster.u32 %0, %1, %2;" : "=r"(rem) : "r"(dst), "r"(0u));
            asm volatile("st.shared::cluster.f32 [%0], %1;" :: "r"(rem), "f"(contrib) : "memory");
            uint32_t mb = smem_u32(&sMbar);
            uint32_t remb;
            asm("mapa.shared::cluster.u32 %0, %1, %2;" : "=r"(remb) : "r"(mb), "r"(0u));
            asm volatile("mbarrier.arrive.release.cluster.shared::cluster.b64 _, [%0];"
                         :: "r"(remb) : "memory");
        }
    }

    // ================= RANK-0 EPILOGUE (others exit immediately) =============
    if (rank == 0 && tid < 256) {
        const uint32_t mb = smem_u32(&sMbar);
        asm volatile(
            "{\n\t.reg .pred P;\n\t"
            "W%=:\n\t"
            "mbarrier.try_wait.parity.acquire.cluster.shared::cta.b64 P, [%0], %1, 0x989680;\n\t"
            "@!P bra W%=;\n\t}"
            :: "r"(mb), "r"(0u) : "memory");
        const int a = tid >> 4;
        const int o = tid & 15;
        float acc = 0.f;
#pragma unroll
        for (int cc = 0; cc < CC; cc++)
            acc += sAll[cc * 16 + o];
        out[a * 256 + n * 16 + o] = acc + bval;
    }
}

extern "C" void kernel_launch(void* const* d_in, const int* in_sizes, int n_in,
                              void* d_out, int out_size)
{
    const float* x = (const float*)d_in[0];
    const float* W = (const float*)d_in[1];
    const float* B = (const float*)d_in[2];
    float* out = (float*)d_out;
    tvar_cluster<<<NN * CLUSTER, 512>>>(x, W, B, out);
}